// round 10
// baseline (speedup 1.0000x reference)
#include <cuda_runtime.h>

// SpatialTransformer: affine grid + bilinear sampling.
// 2-row-per-iteration oy walk: the four bottom-row corner loads of rows k,k+1
// are issued as one straight-line batch (high MLP, no branches); top-row
// corners reuse the previous bottom pair (register copy) when the integer
// corner key matches, else rare fallback loads. Corner clamping done in the
// float pipe so the clipped-corner weights need no I2F.
// image: [B=16, H=256, W=256, C=64] fp32, theta: [B=16, 6], out same shape.

constexpr int B_  = 16;
constexpr int H_  = 256;
constexpr int W_  = 256;
constexpr int C_  = 64;
constexpr int OH_ = 256;
constexpr int OW_ = 256;
constexpr int K_  = 8;   // oy pixels per thread (OH_/K_ = 32 strips)

__global__ __launch_bounds__(256) void stn_kernel(
    const float* __restrict__ img,
    const float* __restrict__ theta,
    float* __restrict__ out)
{
    const int gid = blockIdx.x * blockDim.x + threadIdx.x;
    const int c4  = gid & 15;          // float4 chunk (4 channels)
    const int t   = gid >> 4;          // pixel-column index
    const int ox  = t & (OW_ - 1);
    const int t2  = t >> 8;
    const int oyb = (t2 & (OH_ / K_ - 1)) * K_;
    const int b   = t2 >> 5;           // OH_/K_ = 32 -> shift 5

    const float th0 = __ldg(theta + b * 6 + 0);
    const float th1 = __ldg(theta + b * 6 + 1);
    const float th2 = __ldg(theta + b * 6 + 2);
    const float th3 = __ldg(theta + b * 6 + 3);
    const float th4 = __ldg(theta + b * 6 + 4);
    const float th5 = __ldg(theta + b * 6 + 5);

    // xt = th1*ys + (th0*xs + th2),  yt = th4*ys + (th3*xs + th5)
    const float xs = fmaf((float)ox, 2.0f / (OW_ - 1), -1.0f);
    const float xc = fmaf(th0, xs, th2);
    const float yc = fmaf(th3, xs, th5);

    // batch-folded base; per-texel float4 offset = (iy<<12) | (ix<<4)
    const float4* __restrict__ imgb =
        (const float4*)img + c4 + b * (H_ * W_ * (C_ / 4));
    float4* __restrict__ out4 =
        (float4*)out + (((b * OH_ + oyb) * OW_ + ox) * (C_ / 4) + c4);

    float4 Pb, Pd;
    Pb = Pd = make_float4(0.f, 0.f, 0.f, 0.f);
    int pkey = -1;

#pragma unroll
    for (int k = 0; k < K_; k += 2) {
        // ---- coordinate math for rows k (A) and k+1 (B) ----
        const float ysA = fmaf((float)(oyb + k),     2.0f / (OH_ - 1), -1.0f);
        const float ysB = fmaf((float)(oyb + k + 1), 2.0f / (OH_ - 1), -1.0f);
        const float xA = (fmaf(th1, ysA, xc) + 1.0f) * (0.5f * (float)W_);
        const float yA = (fmaf(th4, ysA, yc) + 1.0f) * (0.5f * (float)H_);
        const float xB = (fmaf(th1, ysB, xc) + 1.0f) * (0.5f * (float)W_);
        const float yB = (fmaf(th4, ysB, yc) + 1.0f) * (0.5f * (float)H_);

        const float xfA = floorf(xA), yfA = floorf(yA);
        const float xfB = floorf(xB), yfB = floorf(yB);

        // clamp in float pipe; these ARE the clipped-corner weights' floats
        const float x0fA = fminf(fmaxf(xfA,        0.f), (float)(W_ - 1));
        const float x1fA = fminf(fmaxf(xfA + 1.f,  0.f), (float)(W_ - 1));
        const float y0fA = fminf(fmaxf(yfA,        0.f), (float)(H_ - 1));
        const float y1fA = fminf(fmaxf(yfA + 1.f,  0.f), (float)(H_ - 1));
        const float x0fB = fminf(fmaxf(xfB,        0.f), (float)(W_ - 1));
        const float x1fB = fminf(fmaxf(xfB + 1.f,  0.f), (float)(W_ - 1));
        const float y0fB = fminf(fmaxf(yfB,        0.f), (float)(H_ - 1));
        const float y1fB = fminf(fmaxf(yfB + 1.f,  0.f), (float)(H_ - 1));

        const int ix0A = (int)x0fA, ix1A = (int)x1fA;
        const int iy0A = (int)y0fA, iy1A = (int)y1fA;
        const int ix0B = (int)x0fB, ix1B = (int)x1fB;
        const int iy0B = (int)y0fB, iy1B = (int)y1fB;

        const int cA0 = ix0A << 4, cA1 = ix1A << 4;
        const int rA0 = iy0A << 12, rA1 = iy1A << 12;
        const int cB0 = ix0B << 4, cB1 = ix1B << 4;
        const int rB0 = iy0B << 12, rB1 = iy1B << 12;

        // ---- 4 batched, branch-free bottom-row loads ----
        const float4 NbA = __ldg(imgb + rA1 + cA0);
        const float4 NdA = __ldg(imgb + rA1 + cA1);
        const float4 NbB = __ldg(imgb + rB1 + cB0);
        const float4 NdB = __ldg(imgb + rB1 + cB1);

        const int keyTA = ix0A | (ix1A << 8) | (iy0A << 16);
        const int keyBA = ix0A | (ix1A << 8) | (iy1A << 16);
        const int keyTB = ix0B | (ix1B << 8) | (iy0B << 16);
        const int keyBB = ix0B | (ix1B << 8) | (iy1B << 16);

        // ---- conditional top-row corners (rare fallback loads) ----
        float4 NaA, NcA;
        if (keyTA == pkey) { NaA = Pb; NcA = Pd; }
        else {
            NaA = __ldg(imgb + rA0 + cA0);
            NcA = __ldg(imgb + rA0 + cA1);
        }
        float4 NaB, NcB;
        if (keyTB == keyBA) { NaB = NbA; NcB = NdA; }
        else {
            NaB = __ldg(imgb + rB0 + cB0);
            NcB = __ldg(imgb + rB0 + cB1);
        }

        // ---- blend + store row A ----
        {
            const float wa = (x1fA - xA) * (y1fA - yA);
            const float wb = (x1fA - xA) * (yA - y0fA);
            const float wc = (xA - x0fA) * (y1fA - yA);
            const float wd = (xA - x0fA) * (yA - y0fA);
            float4 o;
            o.x = fmaf(wa, NaA.x, fmaf(wb, NbA.x, fmaf(wc, NcA.x, wd * NdA.x)));
            o.y = fmaf(wa, NaA.y, fmaf(wb, NbA.y, fmaf(wc, NcA.y, wd * NdA.y)));
            o.z = fmaf(wa, NaA.z, fmaf(wb, NbA.z, fmaf(wc, NcA.z, wd * NdA.z)));
            o.w = fmaf(wa, NaA.w, fmaf(wb, NbA.w, fmaf(wc, NcA.w, wd * NdA.w)));
            *out4 = o;
            out4 += OW_ * (C_ / 4);
        }
        // ---- blend + store row B ----
        {
            const float wa = (x1fB - xB) * (y1fB - yB);
            const float wb = (x1fB - xB) * (yB - y0fB);
            const float wc = (xB - x0fB) * (y1fB - yB);
            const float wd = (xB - x0fB) * (yB - y0fB);
            float4 o;
            o.x = fmaf(wa, NaB.x, fmaf(wb, NbB.x, fmaf(wc, NcB.x, wd * NdB.x)));
            o.y = fmaf(wa, NaB.y, fmaf(wb, NbB.y, fmaf(wc, NcB.y, wd * NdB.y)));
            o.z = fmaf(wa, NaB.z, fmaf(wb, NbB.z, fmaf(wc, NcB.z, wd * NdB.z)));
            o.w = fmaf(wa, NaB.w, fmaf(wb, NbB.w, fmaf(wc, NcB.w, wd * NdB.w)));
            *out4 = o;
            out4 += OW_ * (C_ / 4);
        }

        Pb = NbB; Pd = NdB; pkey = keyBB;
    }
}

extern "C" void kernel_launch(void* const* d_in, const int* in_sizes, int n_in,
                              void* d_out, int out_size)
{
    const float* img   = (const float*)d_in[0];
    const float* theta = (const float*)d_in[1];
    float* out = (float*)d_out;

    // threads = B*OW*(OH/K)*16 = 16*256*32*16 = 2,097,152 -> 8192 blocks
    const int threads = 256;
    const int blocks  = (B_ * OW_ * (OH_ / K_) * 16) / threads;

    stn_kernel<<<blocks, threads>>>(img, theta, out);
}